// round 6
// baseline (speedup 1.0000x reference)
#include <cuda_runtime.h>
#include <cuda_fp16.h>

#define NUM_ENTITIES 200000
#define NEG_INF -9e15f
#define ALPHA 0.2f
#define DDIM 64
#define MNB 16
#define NREL 51
#define FULLMASK 0xffffffffu

// Fused per-relation projection table in fp16, lane-interleaved:
// g_uh[r*128 + lane*4 + {0,1,2,3}] = { u1[2l], u1[2l+1], u2[2l], u2[2l+1] }
// where u1[k] = sum_d fc_W[k,d]*rel[r,d], u2[k] = sum_d fc_W[k+64,d]*rel[r,d].
__device__ __align__(8) __half g_uh[NREL * 2 * DDIM];
__device__ float g_c[NREL];           // c[r] = dot(fc_b, rel[r])

// 51 blocks x 64 threads: thread k computes u1[k], u2[k] for relation r.
__global__ void precompute_kernel(const float* __restrict__ fc_W,
                                  const float* __restrict__ fc_b,
                                  const float* __restrict__ rel_table) {
    __shared__ float rel[DDIM];
    const int r = blockIdx.x;
    const int k = threadIdx.x;

    const float rv_k = rel_table[r * DDIM + k];
    rel[k] = rv_k;
    __syncthreads();

    float s1 = 0.f, s2 = 0.f;
#pragma unroll 8
    for (int d = 0; d < DDIM; d++) {
        float rv = rel[d];
        s1 = fmaf(fc_W[k * DDIM + d], rv, s1);
        s2 = fmaf(fc_W[(k + DDIM) * DDIM + d], rv, s2);
    }
    const int base = r * 2 * DDIM + (k >> 1) * 4 + (k & 1);
    g_uh[base]     = __float2half(s1);
    g_uh[base + 2] = __float2half(s2);

    float bp = fc_b[k] * rv_k;
    bp += __shfl_xor_sync(FULLMASK, bp, 16);
    bp += __shfl_xor_sync(FULLMASK, bp, 8);
    bp += __shfl_xor_sync(FULLMASK, bp, 4);
    bp += __shfl_xor_sync(FULLMASK, bp, 2);
    bp += __shfl_xor_sync(FULLMASK, bp, 1);
    __shared__ float warp_sum[2];
    if ((k & 31) == 0) warp_sum[k >> 5] = bp;
    __syncthreads();
    if (k == 0) g_c[r] = warp_sum[0] + warp_sum[1];
}

// One 64-thread block per item row; each warp handles 8 of the 16 neighbors.
// Lane owns dims [2*lane, 2*lane+1].
__global__ void __launch_bounds__(64, 16)
gat_kernel(const int* __restrict__ item_ids,
           const int* __restrict__ item_entities,
           const int* __restrict__ item_relations,
           const float* __restrict__ item_table,
           const float* __restrict__ entity_table,
           float* __restrict__ out,
           int N) {
    const int row  = blockIdx.x;
    const int wid  = threadIdx.x >> 5;   // 0 or 1: which 8-neighbor half
    const int lane = threadIdx.x & 31;
    if (row >= N) return;                // uniform across block

    __shared__ float  s_logit[MNB];
    __shared__ float2 s_acc[32];

    const int iid = __ldg(item_ids + row);
    const float2 it = *(const float2*)(item_table + iid * DDIM + 2 * lane);

    // Lanes 0..7 hold this warp's 8 (entity, relation) ids.
    int my_eid = 0, my_rid = 0;
    if (lane < 8) {
        my_eid = __ldg(item_entities + row * MNB + 8 * wid + lane);
        my_rid = __ldg(item_relations + row * MNB + 8 * wid + lane);
    }

    // ---- Phase 1: batched gathers + per-lane partial dots (8 m) ----
    float2 ent[8];
    float  pl[8];
#pragma unroll
    for (int m = 0; m < 8; m++) {
        const int eid = __shfl_sync(FULLMASK, my_eid, m);
        ent[m] = *(const float2*)(entity_table + eid * DDIM + 2 * lane);
    }
#pragma unroll
    for (int m = 0; m < 8; m++) {
        const int rid = __shfl_sync(FULLMASK, my_rid, m);
        const __half2* up = (const __half2*)(g_uh + rid * 2 * DDIM + 4 * lane);
        const float2 u1 = __half22float2(up[0]);
        const float2 u2 = __half22float2(up[1]);
        pl[m] = it.x * u1.x + it.y * u1.y + ent[m].x * u2.x + ent[m].y * u2.y;
    }

    // ---- Phase 2: merge tree, 8 values via lane bits {8,4,2}; then pure
    // reduction over offsets {16,1}. Lane l ends with sum of value (l>>1)&7.
    const bool h8 = lane & 8, h4 = lane & 4, h2 = lane & 2;
#pragma unroll
    for (int i = 0; i < 4; i++) {
        float a = pl[i]     + __shfl_xor_sync(FULLMASK, pl[i],     8);
        float b = pl[i + 4] + __shfl_xor_sync(FULLMASK, pl[i + 4], 8);
        pl[i] = h8 ? b : a;
    }
#pragma unroll
    for (int i = 0; i < 2; i++) {
        float a = pl[i]     + __shfl_xor_sync(FULLMASK, pl[i],     4);
        float b = pl[i + 2] + __shfl_xor_sync(FULLMASK, pl[i + 2], 4);
        pl[i] = h4 ? b : a;
    }
    float a0 = pl[0] + __shfl_xor_sync(FULLMASK, pl[0], 2);
    float b0 = pl[1] + __shfl_xor_sync(FULLMASK, pl[1], 2);
    float e = h2 ? b0 : a0;
    e += __shfl_xor_sync(FULLMASK, e, 16);
    e += __shfl_xor_sync(FULLMASK, e, 1);

    // ---- Epilogue: logit for local value v = (lane>>1)&7 ----
    const int src = (lane >> 1) & 7;
    const int rid_v = __shfl_sync(FULLMASK, my_rid, src);
    const int eid_v = __shfl_sync(FULLMASK, my_eid, src);
    e += __ldg(g_c + rid_v);
    e = (e > 0.f) ? e : ALPHA * e;                     // leaky_relu
    e = (eid_v != NUM_ENTITIES) ? e : NEG_INF;         // padding mask

    // Exchange logits between the two warps via smem.
    if (lane < 16 && (lane & 1) == 0)
        s_logit[8 * wid + (lane >> 1)] = e;
    __syncthreads();

    // ---- Softmax over all 16 values (lane l works on value lane&15) ----
    const float lv = s_logit[lane & 15];
    float mx = lv;
    mx = fmaxf(mx, __shfl_xor_sync(FULLMASK, mx, 8));
    mx = fmaxf(mx, __shfl_xor_sync(FULLMASK, mx, 4));
    mx = fmaxf(mx, __shfl_xor_sync(FULLMASK, mx, 2));
    mx = fmaxf(mx, __shfl_xor_sync(FULLMASK, mx, 1));
    const float ex = __expf(lv - mx);
    float s = ex;
    s += __shfl_xor_sync(FULLMASK, s, 8);
    s += __shfl_xor_sync(FULLMASK, s, 4);
    s += __shfl_xor_sync(FULLMASK, s, 2);
    s += __shfl_xor_sync(FULLMASK, s, 1);
    const float w = __fdividef(ex, s);   // lane l: weight of value lane&15

    // ---- Partial weighted sum over this warp's 8 entities ----
    float2 acc = make_float2(0.f, 0.f);
#pragma unroll
    for (int m = 0; m < 8; m++) {
        const float wm = __shfl_sync(FULLMASK, w, 8 * wid + m);
        acc.x = fmaf(wm, ent[m].x, acc.x);
        acc.y = fmaf(wm, ent[m].y, acc.y);
    }

    // ---- Combine warp partials + residual, write out ----
    if (wid == 1) s_acc[lane] = acc;
    __syncthreads();
    if (wid == 0) {
        const float2 o = s_acc[lane];
        acc.x += o.x + it.x;
        acc.y += o.y + it.y;
        *(float2*)(out + row * DDIM + 2 * lane) = acc;
    }
}

extern "C" void kernel_launch(void* const* d_in, const int* in_sizes, int n_in,
                              void* d_out, int out_size) {
    const int*   item_ids       = (const int*)d_in[0];
    const int*   item_entities  = (const int*)d_in[1];
    const int*   item_relations = (const int*)d_in[2];
    const float* item_table     = (const float*)d_in[3];
    const float* entity_table   = (const float*)d_in[4];
    const float* relation_table = (const float*)d_in[5];
    const float* fc_W           = (const float*)d_in[6];
    const float* fc_b           = (const float*)d_in[7];
    float* out = (float*)d_out;

    const int N = in_sizes[0];

    precompute_kernel<<<NREL, DDIM>>>(fc_W, fc_b, relation_table);

    // One 64-thread block (2 warps) per row.
    gat_kernel<<<N, 64>>>(item_ids, item_entities, item_relations,
                          item_table, entity_table, out, N);
}

// round 9
// speedup vs baseline: 1.1624x; 1.1624x over previous
#include <cuda_runtime.h>
#include <cuda_fp16.h>

#define NUM_ENTITIES 200000
#define NEG_INF -9e15f
#define ALPHA 0.2f
#define DDIM 64
#define MNB 16
#define NREL 51
#define FULLMASK 0xffffffffu

// Fused per-relation projection table in fp16, 16B per lane (lanes 0..15):
// g_uh[r*128 + l*8 + {0..3}] = u1[4l..4l+3], g_uh[r*128 + l*8 + {4..7}] = u2[4l..4l+3]
// where u1[k] = sum_d fc_W[k,d]*rel[r,d], u2[k] = sum_d fc_W[k+64,d]*rel[r,d].
__device__ __align__(16) __half g_uh[NREL * 2 * DDIM];
__device__ float g_c[NREL];           // c[r] = dot(fc_b, rel[r])

// 51 blocks x 64 threads: thread k computes u1[k], u2[k] for relation r.
__global__ void precompute_kernel(const float* __restrict__ fc_W,
                                  const float* __restrict__ fc_b,
                                  const float* __restrict__ rel_table) {
    __shared__ float rel[DDIM];
    const int r = blockIdx.x;
    const int k = threadIdx.x;

    const float rv_k = rel_table[r * DDIM + k];
    rel[k] = rv_k;
    __syncthreads();

    float s1 = 0.f, s2 = 0.f;
#pragma unroll 8
    for (int d = 0; d < DDIM; d++) {
        float rv = rel[d];
        s1 = fmaf(fc_W[k * DDIM + d], rv, s1);
        s2 = fmaf(fc_W[(k + DDIM) * DDIM + d], rv, s2);
    }
    // l = k>>2 (owning lane), j = k&3 (dim within lane's float4 group)
    const int base = r * 2 * DDIM + (k >> 2) * 8 + (k & 3);
    g_uh[base]     = __float2half(s1);
    g_uh[base + 4] = __float2half(s2);

    float bp = fc_b[k] * rv_k;
    bp += __shfl_xor_sync(FULLMASK, bp, 16);
    bp += __shfl_xor_sync(FULLMASK, bp, 8);
    bp += __shfl_xor_sync(FULLMASK, bp, 4);
    bp += __shfl_xor_sync(FULLMASK, bp, 2);
    bp += __shfl_xor_sync(FULLMASK, bp, 1);
    __shared__ float warp_sum[2];
    if ((k & 31) == 0) warp_sum[k >> 5] = bp;
    __syncthreads();
    if (k == 0) g_c[r] = warp_sum[0] + warp_sum[1];
}

// One warp per item row. Lane owns dims [4*(lane&15) .. +3].
// Lanes 0-15 service even neighbors, lanes 16-31 odd neighbors:
// load i covers entities {2i, 2i+1} in a single LDG.128 across the warp.
__global__ void __launch_bounds__(256, 3)
gat_kernel(const int* __restrict__ item_ids,
           const int* __restrict__ item_entities,
           const int* __restrict__ item_relations,
           const float* __restrict__ item_table,
           const float* __restrict__ entity_table,
           float* __restrict__ out,
           int N) {
    const int warp = (int)((blockIdx.x * blockDim.x + threadIdx.x) >> 5);
    const int lane = threadIdx.x & 31;
    if (warp >= N) return;

    const int half = lane >> 4;          // 0: even entities, 1: odd entities
    const int dlane = lane & 15;         // dim-group owner within half

    const int iid = __ldg(item_ids + warp);
    const float4 it = *(const float4*)(item_table + iid * DDIM + 4 * dlane);

    // Lanes 0..15 hold the 16 neighbor (entity, relation) ids.
    int my_eid = 0, my_rid = 0;
    if (lane < MNB) {
        my_eid = __ldg(item_entities + warp * MNB + lane);
        my_rid = __ldg(item_relations + warp * MNB + lane);
    }

    // ---- Phase 1: 8 paired gathers + per-lane partial dots ----
    float4 ent[8];
    float  pl[8];
#pragma unroll
    for (int i = 0; i < 8; i++) {
        const int eid = __shfl_sync(FULLMASK, my_eid, 2 * i + half);
        ent[i] = *(const float4*)(entity_table + eid * DDIM + 4 * dlane);
    }
#pragma unroll
    for (int i = 0; i < 8; i++) {
        const int rid = __shfl_sync(FULLMASK, my_rid, 2 * i + half);
        const uint4 u = *(const uint4*)(g_uh + rid * 2 * DDIM + 8 * dlane);
        const float2 u1a = __half22float2(*(const __half2*)&u.x);
        const float2 u1b = __half22float2(*(const __half2*)&u.y);
        const float2 u2a = __half22float2(*(const __half2*)&u.z);
        const float2 u2b = __half22float2(*(const __half2*)&u.w);
        float p;
        p = it.x * u1a.x;
        p = fmaf(it.y, u1a.y, p);
        p = fmaf(it.z, u1b.x, p);
        p = fmaf(it.w, u1b.y, p);
        p = fmaf(ent[i].x, u2a.x, p);
        p = fmaf(ent[i].y, u2a.y, p);
        p = fmaf(ent[i].z, u2b.x, p);
        p = fmaf(ent[i].w, u2b.y, p);
        pl[i] = p;
    }

    // ---- Phase 2: merge tree over lane bits {3,2,1}; butterfly over bit 0.
    // After all stages lane l holds the 16-lane sum (within its half) of local
    // value idx = 4*b3(l) + 2*b2(l) + b1(l); global value v = 2*idx + half.
    const bool b3 = lane & 8, b2 = lane & 4, b1 = lane & 2;
#pragma unroll
    for (int i = 0; i < 4; i++) {          // offset 8: 8 -> 4
        float a = pl[i]     + __shfl_xor_sync(FULLMASK, pl[i],     8);
        float b = pl[i + 4] + __shfl_xor_sync(FULLMASK, pl[i + 4], 8);
        pl[i] = b3 ? b : a;
    }
#pragma unroll
    for (int i = 0; i < 2; i++) {          // offset 4: 4 -> 2
        float a = pl[i]     + __shfl_xor_sync(FULLMASK, pl[i],     4);
        float b = pl[i + 2] + __shfl_xor_sync(FULLMASK, pl[i + 2], 4);
        pl[i] = b2 ? b : a;
    }
    float a0 = pl[0] + __shfl_xor_sync(FULLMASK, pl[0], 2);   // offset 2: 2 -> 1
    float b0 = pl[1] + __shfl_xor_sync(FULLMASK, pl[1], 2);
    float e = b1 ? b0 : a0;
    e += __shfl_xor_sync(FULLMASK, e, 1);                     // bit 0

    // ---- Epilogue: one logit per lane for its value v ----
    const int v = 2 * ((b3 ? 4 : 0) | (b2 ? 2 : 0) | (b1 ? 1 : 0)) + half;
    const int rid_v = __shfl_sync(FULLMASK, my_rid, v);
    const int eid_v = __shfl_sync(FULLMASK, my_eid, v);
    e += __ldg(g_c + rid_v);
    e = (e > 0.f) ? e : ALPHA * e;                     // leaky_relu
    e = (eid_v != NUM_ENTITIES) ? e : NEG_INF;         // padding mask

    // Softmax over the 16 distinct values: v spans lane bits {1,2,3,4},
    // duplicated over bit 0 -> reduce offsets {2,4,8,16}.
    float mx = e;
    mx = fmaxf(mx, __shfl_xor_sync(FULLMASK, mx, 2));
    mx = fmaxf(mx, __shfl_xor_sync(FULLMASK, mx, 4));
    mx = fmaxf(mx, __shfl_xor_sync(FULLMASK, mx, 8));
    mx = fmaxf(mx, __shfl_xor_sync(FULLMASK, mx, 16));
    const float ex = __expf(e - mx);
    float s = ex;
    s += __shfl_xor_sync(FULLMASK, s, 2);
    s += __shfl_xor_sync(FULLMASK, s, 4);
    s += __shfl_xor_sync(FULLMASK, s, 8);
    s += __shfl_xor_sync(FULLMASK, s, 16);
    const float w = __fdividef(ex, s);   // lane l holds weight of its value v

    // ---- Weighted sum over this half's 8 entities ----
    // Weight of global value 2i+half lives on the lane whose tree bits encode
    // idx=i in the SAME order the merge tree used (MSB of i on lane bit 3):
    //   lane = ((i>>2)&1)<<3 | ((i>>1)&1)<<2 | (i&1)<<1 | half<<4.
    float4 acc = make_float4(0.f, 0.f, 0.f, 0.f);
#pragma unroll
    for (int i = 0; i < 8; i++) {
        const int ii = (((i >> 2) & 1) << 3) | (((i >> 1) & 1) << 2) | ((i & 1) << 1);
        const float wm = __shfl_sync(FULLMASK, w, ii + (lane & 16));
        acc.x = fmaf(wm, ent[i].x, acc.x);
        acc.y = fmaf(wm, ent[i].y, acc.y);
        acc.z = fmaf(wm, ent[i].z, acc.z);
        acc.w = fmaf(wm, ent[i].w, acc.w);
    }

    // Combine even/odd halves (lane l <-> l^16 hold same dims) + residual.
    acc.x += __shfl_xor_sync(FULLMASK, acc.x, 16);
    acc.y += __shfl_xor_sync(FULLMASK, acc.y, 16);
    acc.z += __shfl_xor_sync(FULLMASK, acc.z, 16);
    acc.w += __shfl_xor_sync(FULLMASK, acc.w, 16);
    if (lane < 16) {
        acc.x += it.x; acc.y += it.y; acc.z += it.z; acc.w += it.w;
        *(float4*)(out + warp * DDIM + 4 * dlane) = acc;
    }
}

extern "C" void kernel_launch(void* const* d_in, const int* in_sizes, int n_in,
                              void* d_out, int out_size) {
    const int*   item_ids       = (const int*)d_in[0];
    const int*   item_entities  = (const int*)d_in[1];
    const int*   item_relations = (const int*)d_in[2];
    const float* item_table     = (const float*)d_in[3];
    const float* entity_table   = (const float*)d_in[4];
    const float* relation_table = (const float*)d_in[5];
    const float* fc_W           = (const float*)d_in[6];
    const float* fc_b           = (const float*)d_in[7];
    float* out = (float*)d_out;

    const int N = in_sizes[0];

    precompute_kernel<<<NREL, DDIM>>>(fc_W, fc_b, relation_table);

    // One warp per row: 8 rows per 256-thread block.
    const int blocks = (N + 7) / 8;
    gat_kernel<<<blocks, 256>>>(item_ids, item_entities, item_relations,
                                item_table, entity_table, out, N);
}

// round 10
// speedup vs baseline: 1.2152x; 1.0455x over previous
#include <cuda_runtime.h>
#include <cuda_fp16.h>

#define NUM_ENTITIES 200000
#define NEG_INF -9e15f
#define ALPHA 0.2f
#define DDIM 64
#define MNB 16
#define NREL 51
#define FULLMASK 0xffffffffu

// Fused per-relation projection table in fp16, 16B per lane (lanes 0..15):
// g_uh[r*128 + l*8 + {0..3}] = u1[4l..4l+3], g_uh[r*128 + l*8 + {4..7}] = u2[4l..4l+3]
// where u1[k] = sum_d fc_W[k,d]*rel[r,d], u2[k] = sum_d fc_W[k+64,d]*rel[r,d].
__device__ __align__(16) __half g_uh[NREL * 2 * DDIM];
__device__ float g_c[NREL];           // c[r] = dot(fc_b, rel[r])

// 51 blocks x 64 threads: thread k computes u1[k], u2[k] for relation r.
__global__ void precompute_kernel(const float* __restrict__ fc_W,
                                  const float* __restrict__ fc_b,
                                  const float* __restrict__ rel_table) {
    __shared__ float rel[DDIM];
    const int r = blockIdx.x;
    const int k = threadIdx.x;

    const float rv_k = rel_table[r * DDIM + k];
    rel[k] = rv_k;
    __syncthreads();

    float s1 = 0.f, s2 = 0.f;
#pragma unroll 8
    for (int d = 0; d < DDIM; d++) {
        float rv = rel[d];
        s1 = fmaf(fc_W[k * DDIM + d], rv, s1);
        s2 = fmaf(fc_W[(k + DDIM) * DDIM + d], rv, s2);
    }
    // l = k>>2 (owning lane), j = k&3 (dim within lane's float4 group)
    const int base = r * 2 * DDIM + (k >> 2) * 8 + (k & 3);
    g_uh[base]     = __float2half(s1);
    g_uh[base + 4] = __float2half(s2);

    float bp = fc_b[k] * rv_k;
    bp += __shfl_xor_sync(FULLMASK, bp, 16);
    bp += __shfl_xor_sync(FULLMASK, bp, 8);
    bp += __shfl_xor_sync(FULLMASK, bp, 4);
    bp += __shfl_xor_sync(FULLMASK, bp, 2);
    bp += __shfl_xor_sync(FULLMASK, bp, 1);
    __shared__ float warp_sum[2];
    if ((k & 31) == 0) warp_sum[k >> 5] = bp;
    __syncthreads();
    if (k == 0) g_c[r] = warp_sum[0] + warp_sum[1];
}

// One warp per item row. Lane owns dims [4*(lane&15) .. +3].
// Lanes 0-15 service even neighbors, lanes 16-31 odd neighbors.
// Entity vectors are packed to fp16 on load (16 regs instead of 32) so the
// kernel fits 64 regs -> 4 blocks/SM.
__global__ void __launch_bounds__(256, 4)
gat_kernel(const int* __restrict__ item_ids,
           const int* __restrict__ item_entities,
           const int* __restrict__ item_relations,
           const float* __restrict__ item_table,
           const float* __restrict__ entity_table,
           float* __restrict__ out,
           int N) {
    const int warp = (int)((blockIdx.x * blockDim.x + threadIdx.x) >> 5);
    const int lane = threadIdx.x & 31;
    if (warp >= N) return;

    const int half = lane >> 4;          // 0: even entities, 1: odd entities
    const int dlane = lane & 15;         // dim-group owner within half

    const int iid = __ldg(item_ids + warp);
    const float4 it = *(const float4*)(item_table + iid * DDIM + 4 * dlane);

    // Single unpredicated id load: lanes 0..15 -> entity ids, 16..31 -> relation ids.
    const int* idp = (lane < MNB) ? (item_entities + warp * MNB + lane)
                                  : (item_relations + warp * MNB + lane - MNB);
    const int my_id = __ldg(idp);

    // ---- Phase 1: 8 paired gathers, pack to fp16 immediately ----
    __half2 ent_h[8][2];
#pragma unroll
    for (int i = 0; i < 8; i++) {
        const int eid = __shfl_sync(FULLMASK, my_id, 2 * i + half);
        const float4 e = *(const float4*)(entity_table + eid * DDIM + 4 * dlane);
        ent_h[i][0] = __floats2half2_rn(e.x, e.y);
        ent_h[i][1] = __floats2half2_rn(e.z, e.w);
    }

    // ---- Phase 1b: u-table loads + per-lane partial dots ----
    float pl[8];
#pragma unroll
    for (int i = 0; i < 8; i++) {
        const int rid = __shfl_sync(FULLMASK, my_id, MNB + 2 * i + half);
        const uint4 u = *(const uint4*)(g_uh + rid * 2 * DDIM + 8 * dlane);
        const float2 u1a = __half22float2(*(const __half2*)&u.x);
        const float2 u1b = __half22float2(*(const __half2*)&u.y);
        const float2 u2a = __half22float2(*(const __half2*)&u.z);
        const float2 u2b = __half22float2(*(const __half2*)&u.w);
        const float2 exy = __half22float2(ent_h[i][0]);
        const float2 ezw = __half22float2(ent_h[i][1]);
        float p;
        p = it.x * u1a.x;
        p = fmaf(it.y, u1a.y, p);
        p = fmaf(it.z, u1b.x, p);
        p = fmaf(it.w, u1b.y, p);
        p = fmaf(exy.x, u2a.x, p);
        p = fmaf(exy.y, u2a.y, p);
        p = fmaf(ezw.x, u2b.x, p);
        p = fmaf(ezw.y, u2b.y, p);
        pl[i] = p;
    }

    // ---- Phase 2: merge tree over lane bits {3,2,1}; butterfly over bit 0.
    // After all stages lane l holds the 16-lane sum (within its half) of local
    // value idx = 4*b3(l) + 2*b2(l) + b1(l); global value v = 2*idx + half.
    const bool b3 = lane & 8, b2 = lane & 4, b1 = lane & 2;
#pragma unroll
    for (int i = 0; i < 4; i++) {          // offset 8: 8 -> 4
        float a = pl[i]     + __shfl_xor_sync(FULLMASK, pl[i],     8);
        float b = pl[i + 4] + __shfl_xor_sync(FULLMASK, pl[i + 4], 8);
        pl[i] = b3 ? b : a;
    }
#pragma unroll
    for (int i = 0; i < 2; i++) {          // offset 4: 4 -> 2
        float a = pl[i]     + __shfl_xor_sync(FULLMASK, pl[i],     4);
        float b = pl[i + 2] + __shfl_xor_sync(FULLMASK, pl[i + 2], 4);
        pl[i] = b2 ? b : a;
    }
    float a0 = pl[0] + __shfl_xor_sync(FULLMASK, pl[0], 2);   // offset 2: 2 -> 1
    float b0 = pl[1] + __shfl_xor_sync(FULLMASK, pl[1], 2);
    float e = b1 ? b0 : a0;
    e += __shfl_xor_sync(FULLMASK, e, 1);                     // bit 0

    // ---- Epilogue: one logit per lane for its value v ----
    const int v = 2 * ((b3 ? 4 : 0) | (b2 ? 2 : 0) | (b1 ? 1 : 0)) + half;
    const int rid_v = __shfl_sync(FULLMASK, my_id, MNB + v);
    const int eid_v = __shfl_sync(FULLMASK, my_id, v);
    e += __ldg(g_c + rid_v);
    e = (e > 0.f) ? e : ALPHA * e;                     // leaky_relu
    e = (eid_v != NUM_ENTITIES) ? e : NEG_INF;         // padding mask

    // Softmax over the 16 distinct values: v spans lane bits {1,2,3,4},
    // duplicated over bit 0 -> reduce offsets {2,4,8,16}.
    float mx = e;
    mx = fmaxf(mx, __shfl_xor_sync(FULLMASK, mx, 2));
    mx = fmaxf(mx, __shfl_xor_sync(FULLMASK, mx, 4));
    mx = fmaxf(mx, __shfl_xor_sync(FULLMASK, mx, 8));
    mx = fmaxf(mx, __shfl_xor_sync(FULLMASK, mx, 16));
    const float ex = __expf(e - mx);
    float s = ex;
    s += __shfl_xor_sync(FULLMASK, s, 2);
    s += __shfl_xor_sync(FULLMASK, s, 4);
    s += __shfl_xor_sync(FULLMASK, s, 8);
    s += __shfl_xor_sync(FULLMASK, s, 16);
    const float w = __fdividef(ex, s);   // lane l holds weight of its value v

    // ---- Weighted sum over this half's 8 entities ----
    // Weight of global value 2i+half lives on the lane whose tree bits encode
    // idx=i in the same order the merge tree used (MSB of i on lane bit 3).
    float4 acc = make_float4(0.f, 0.f, 0.f, 0.f);
#pragma unroll
    for (int i = 0; i < 8; i++) {
        const int ii = (((i >> 2) & 1) << 3) | (((i >> 1) & 1) << 2) | ((i & 1) << 1);
        const float wm = __shfl_sync(FULLMASK, w, ii + (lane & 16));
        const float2 exy = __half22float2(ent_h[i][0]);
        const float2 ezw = __half22float2(ent_h[i][1]);
        acc.x = fmaf(wm, exy.x, acc.x);
        acc.y = fmaf(wm, exy.y, acc.y);
        acc.z = fmaf(wm, ezw.x, acc.z);
        acc.w = fmaf(wm, ezw.y, acc.w);
    }

    // Combine even/odd halves (lane l <-> l^16 hold same dims) + residual.
    acc.x += __shfl_xor_sync(FULLMASK, acc.x, 16);
    acc.y += __shfl_xor_sync(FULLMASK, acc.y, 16);
    acc.z += __shfl_xor_sync(FULLMASK, acc.z, 16);
    acc.w += __shfl_xor_sync(FULLMASK, acc.w, 16);
    if (lane < 16) {
        acc.x += it.x; acc.y += it.y; acc.z += it.z; acc.w += it.w;
        *(float4*)(out + warp * DDIM + 4 * dlane) = acc;
    }
}

extern "C" void kernel_launch(void* const* d_in, const int* in_sizes, int n_in,
                              void* d_out, int out_size) {
    const int*   item_ids       = (const int*)d_in[0];
    const int*   item_entities  = (const int*)d_in[1];
    const int*   item_relations = (const int*)d_in[2];
    const float* item_table     = (const float*)d_in[3];
    const float* entity_table   = (const float*)d_in[4];
    const float* relation_table = (const float*)d_in[5];
    const float* fc_W           = (const float*)d_in[6];
    const float* fc_b           = (const float*)d_in[7];
    float* out = (float*)d_out;

    const int N = in_sizes[0];

    precompute_kernel<<<NREL, DDIM>>>(fc_W, fc_b, relation_table);

    // One warp per row: 8 rows per 256-thread block.
    const int blocks = (N + 7) / 8;
    gat_kernel<<<blocks, 256>>>(item_ids, item_entities, item_relations,
                                item_table, entity_table, out, N);
}

// round 11
// speedup vs baseline: 1.2187x; 1.0028x over previous
#include <cuda_runtime.h>
#include <cuda_fp16.h>

#define NUM_ENTITIES 200000
#define NEG_INF -9e15f
#define ALPHA 0.2f
#define DDIM 64
#define MNB 16
#define NREL 51
#define FULLMASK 0xffffffffu

// Fused per-relation projection table in fp16, 16B per lane (lanes 0..15):
// g_uh[r*128 + l*8 + {0..3}] = u1[4l..4l+3], g_uh[r*128 + l*8 + {4..7}] = u2[4l..4l+3]
// where u1[k] = sum_d fc_W[k,d]*rel[r,d], u2[k] = sum_d fc_W[k+64,d]*rel[r,d].
__device__ __align__(16) __half g_uh[NREL * 2 * DDIM];
__device__ float g_c[NREL];           // c[r] = dot(fc_b, rel[r])

// 51 blocks x 64 threads: thread k computes u1[k], u2[k] for relation r.
__global__ void precompute_kernel(const float* __restrict__ fc_W,
                                  const float* __restrict__ fc_b,
                                  const float* __restrict__ rel_table) {
    __shared__ float rel[DDIM];
    const int r = blockIdx.x;
    const int k = threadIdx.x;

    const float rv_k = rel_table[r * DDIM + k];
    rel[k] = rv_k;
    __syncthreads();

    float s1 = 0.f, s2 = 0.f;
#pragma unroll 8
    for (int d = 0; d < DDIM; d++) {
        float rv = rel[d];
        s1 = fmaf(fc_W[k * DDIM + d], rv, s1);
        s2 = fmaf(fc_W[(k + DDIM) * DDIM + d], rv, s2);
    }
    // l = k>>2 (owning lane), j = k&3 (dim within lane's float4 group)
    const int base = r * 2 * DDIM + (k >> 2) * 8 + (k & 3);
    g_uh[base]     = __float2half(s1);
    g_uh[base + 4] = __float2half(s2);

    float bp = fc_b[k] * rv_k;
    bp += __shfl_xor_sync(FULLMASK, bp, 16);
    bp += __shfl_xor_sync(FULLMASK, bp, 8);
    bp += __shfl_xor_sync(FULLMASK, bp, 4);
    bp += __shfl_xor_sync(FULLMASK, bp, 2);
    bp += __shfl_xor_sync(FULLMASK, bp, 1);
    __shared__ float warp_sum[2];
    if ((k & 31) == 0) warp_sum[k >> 5] = bp;
    __syncthreads();
    if (k == 0) g_c[r] = warp_sum[0] + warp_sum[1];
}

// Grid-stride persistent kernel: one warp per item row per iteration.
// Lane owns dims [4*(lane&15) .. +3]; lanes 0-15 service even neighbors,
// lanes 16-31 odd. Partial dot runs in fp16 (HFMA2); cross-lane accumulation,
// softmax and output stay fp32.
__global__ void __launch_bounds__(256, 4)
gat_kernel(const int* __restrict__ item_ids,
           const int* __restrict__ item_entities,
           const int* __restrict__ item_relations,
           const float* __restrict__ item_table,
           const float* __restrict__ entity_table,
           float* __restrict__ out,
           int N) {
    const int lane  = threadIdx.x & 31;
    const int half  = lane >> 4;         // 0: even entities, 1: odd entities
    const int dlane = lane & 15;         // dim-group owner within half
    const bool b3 = lane & 8, b2 = lane & 4, b1 = lane & 2;
    const int v = 2 * ((b3 ? 4 : 0) | (b2 ? 2 : 0) | (b1 ? 1 : 0)) + half;

    const int warp0   = blockIdx.x * 8 + (threadIdx.x >> 5);
    const int wstride = gridDim.x * 8;

    for (int row = warp0; row < N; row += wstride) {
        const int iid = __ldg(item_ids + row);
        const float4 it = *(const float4*)(item_table + iid * DDIM + 4 * dlane);
        const __half2 it_h0 = __floats2half2_rn(it.x, it.y);
        const __half2 it_h1 = __floats2half2_rn(it.z, it.w);

        // Single id load: lanes 0..15 -> entity ids, 16..31 -> relation ids.
        const int* idp = (lane < MNB) ? (item_entities + row * MNB + lane)
                                      : (item_relations + row * MNB + lane - MNB);
        const int my_id = __ldg(idp);

        // ---- Phase 1: 8 paired gathers, pack to fp16 immediately ----
        __half2 ent_h[8][2];
#pragma unroll
        for (int i = 0; i < 8; i++) {
            const int eid = __shfl_sync(FULLMASK, my_id, 2 * i + half);
            const float4 e = *(const float4*)(entity_table + eid * DDIM + 4 * dlane);
            ent_h[i][0] = __floats2half2_rn(e.x, e.y);
            ent_h[i][1] = __floats2half2_rn(e.z, e.w);
        }

        // ---- Phase 1b: u-table loads + fp16 partial dots ----
        float pl[8];
#pragma unroll
        for (int i = 0; i < 8; i++) {
            const int rid = __shfl_sync(FULLMASK, my_id, MNB + 2 * i + half);
            const uint4 u = *(const uint4*)(g_uh + rid * 2 * DDIM + 8 * dlane);
            __half2 h1 = __hmul2(*(const __half2*)&u.x, it_h0);
            h1 = __hfma2(*(const __half2*)&u.y, it_h1, h1);
            __half2 h2 = __hmul2(*(const __half2*)&u.z, ent_h[i][0]);
            h2 = __hfma2(*(const __half2*)&u.w, ent_h[i][1], h2);
            h1 = __hadd2(h1, h2);
            const float2 pf = __half22float2(h1);
            pl[i] = pf.x + pf.y;
        }

        // ---- Phase 2: merge tree over lane bits {3,2,1}; butterfly bit 0.
        // Lane l ends with the 16-lane sum (within its half) of local value
        // idx = 4*b3 + 2*b2 + b1; global value v = 2*idx + half.
#pragma unroll
        for (int i = 0; i < 4; i++) {          // offset 8: 8 -> 4
            float a = pl[i]     + __shfl_xor_sync(FULLMASK, pl[i],     8);
            float b = pl[i + 4] + __shfl_xor_sync(FULLMASK, pl[i + 4], 8);
            pl[i] = b3 ? b : a;
        }
#pragma unroll
        for (int i = 0; i < 2; i++) {          // offset 4: 4 -> 2
            float a = pl[i]     + __shfl_xor_sync(FULLMASK, pl[i],     4);
            float b = pl[i + 2] + __shfl_xor_sync(FULLMASK, pl[i + 2], 4);
            pl[i] = b2 ? b : a;
        }
        float a0 = pl[0] + __shfl_xor_sync(FULLMASK, pl[0], 2);  // 2 -> 1
        float b0 = pl[1] + __shfl_xor_sync(FULLMASK, pl[1], 2);
        float e = b1 ? b0 : a0;
        e += __shfl_xor_sync(FULLMASK, e, 1);                    // bit 0

        // ---- Epilogue: one logit per lane for its value v ----
        const int rid_v = __shfl_sync(FULLMASK, my_id, MNB + v);
        const int eid_v = __shfl_sync(FULLMASK, my_id, v);
        e += __ldg(g_c + rid_v);
        e = (e > 0.f) ? e : ALPHA * e;                    // leaky_relu
        e = (eid_v != NUM_ENTITIES) ? e : NEG_INF;        // padding mask

        // Softmax over the 16 distinct values: v spans lane bits {1,2,3,4},
        // duplicated over bit 0 -> reduce offsets {2,4,8,16}.
        float mx = e;
        mx = fmaxf(mx, __shfl_xor_sync(FULLMASK, mx, 2));
        mx = fmaxf(mx, __shfl_xor_sync(FULLMASK, mx, 4));
        mx = fmaxf(mx, __shfl_xor_sync(FULLMASK, mx, 8));
        mx = fmaxf(mx, __shfl_xor_sync(FULLMASK, mx, 16));
        const float ex = __expf(e - mx);
        float s = ex;
        s += __shfl_xor_sync(FULLMASK, s, 2);
        s += __shfl_xor_sync(FULLMASK, s, 4);
        s += __shfl_xor_sync(FULLMASK, s, 8);
        s += __shfl_xor_sync(FULLMASK, s, 16);
        const float w = __fdividef(ex, s);  // lane l: weight of its value v

        // ---- Weighted sum (fp32) over this half's 8 entities ----
        // Weight of global value 2i+half lives on the lane whose tree bits
        // encode idx=i in tree order (MSB of i on lane bit 3).
        float4 acc = make_float4(0.f, 0.f, 0.f, 0.f);
#pragma unroll
        for (int i = 0; i < 8; i++) {
            const int ii = (((i >> 2) & 1) << 3) | (((i >> 1) & 1) << 2) | ((i & 1) << 1);
            const float wm = __shfl_sync(FULLMASK, w, ii + (lane & 16));
            const float2 exy = __half22float2(ent_h[i][0]);
            const float2 ezw = __half22float2(ent_h[i][1]);
            acc.x = fmaf(wm, exy.x, acc.x);
            acc.y = fmaf(wm, exy.y, acc.y);
            acc.z = fmaf(wm, ezw.x, acc.z);
            acc.w = fmaf(wm, ezw.y, acc.w);
        }

        // Combine even/odd halves (lane l <-> l^16 same dims) + residual.
        acc.x += __shfl_xor_sync(FULLMASK, acc.x, 16);
        acc.y += __shfl_xor_sync(FULLMASK, acc.y, 16);
        acc.z += __shfl_xor_sync(FULLMASK, acc.z, 16);
        acc.w += __shfl_xor_sync(FULLMASK, acc.w, 16);
        if (lane < 16) {
            acc.x += it.x; acc.y += it.y; acc.z += it.z; acc.w += it.w;
            *(float4*)(out + row * DDIM + 4 * dlane) = acc;
        }
    }
}

extern "C" void kernel_launch(void* const* d_in, const int* in_sizes, int n_in,
                              void* d_out, int out_size) {
    const int*   item_ids       = (const int*)d_in[0];
    const int*   item_entities  = (const int*)d_in[1];
    const int*   item_relations = (const int*)d_in[2];
    const float* item_table     = (const float*)d_in[3];
    const float* entity_table   = (const float*)d_in[4];
    const float* relation_table = (const float*)d_in[5];
    const float* fc_W           = (const float*)d_in[6];
    const float* fc_b           = (const float*)d_in[7];
    float* out = (float*)d_out;

    const int N = in_sizes[0];

    precompute_kernel<<<NREL, DDIM>>>(fc_W, fc_b, relation_table);

    // Persistent grid-stride: 4 blocks/SM x 148 SMs.
    gat_kernel<<<592, 256>>>(item_ids, item_entities, item_relations,
                             item_table, entity_table, out, N);
}